// round 11
// baseline (speedup 1.0000x reference)
#include <cuda_runtime.h>
#include <math.h>

#define TT 512
#define BB 32
#define HH 512
#define GG 2048
#define NIN 64
#define NB 128
#define HB 16384   // HH*BB
#define GB 65536   // GG*BB

// ---- static device scratch (no allocations allowed) ----
__device__ float g_xg0[(size_t)TT * GB];   // xg0 -> activated gates L0 -> dg0 (in place)
__device__ float g_xg1[(size_t)TT * GB];
__device__ float g_c0[(size_t)TT * HB];
__device__ float g_c1[(size_t)TT * HB];
__device__ float g_h0[(size_t)TT * HB];    // [t][k][b]
__device__ float g_h1[(size_t)TT * HB];
__device__ float g_dx1[(size_t)TT * HB];   // dL/d(h0) from layer1 input path

__device__ unsigned g_bar_count = 0;
__device__ unsigned g_bar_gen   = 0;

__device__ __forceinline__ void grid_barrier(unsigned target) {
    __syncthreads();
    if (threadIdx.x == 0) {
        __threadfence();
        unsigned old = atomicAdd(&g_bar_count, 1u);
        if (old == NB - 1) {
            g_bar_count = 0;
            __threadfence();
            atomicExch(&g_bar_gen, target);
        } else {
            while ((int)(*(volatile unsigned*)&g_bar_gen - target) < 0) {}
            __threadfence();
        }
    }
    __syncthreads();
}

__device__ __forceinline__ float sigf(float x) { return 1.0f / (1.0f + expf(-x)); }

// ================= K1: xg0 = x @ W_ih0^T + b_ih0 + b_hh0, layout [t][n][b] =================
__global__ void __launch_bounds__(256) k_xg0(const float* __restrict__ x,
                                             const float* __restrict__ Wih,
                                             const float* __restrict__ bih,
                                             const float* __restrict__ bhh) {
    __shared__ float xs[32 * 65];
    __shared__ float Ws[128 * 64];
    const int tid = threadIdx.x, t = blockIdx.y, n0 = blockIdx.x * 128;
    for (int i = tid; i < 32 * 64; i += 256) {
        int b = i >> 6, k = i & 63;
        xs[b * 65 + k] = x[((size_t)b * TT + t) * NIN + k];
    }
    for (int i = tid; i < 128 * 64; i += 256) {
        int r = i >> 6, k = i & 63;
        Ws[i] = Wih[(size_t)(n0 + r) * NIN + k];
    }
    __syncthreads();
    const int b = tid & 31, ng = tid >> 5;
    float acc[16];
#pragma unroll
    for (int m = 0; m < 16; ++m) acc[m] = 0.f;
    for (int k = 0; k < 64; k += 4) {
        float h0 = xs[b * 65 + k], h1 = xs[b * 65 + k + 1];
        float h2 = xs[b * 65 + k + 2], h3 = xs[b * 65 + k + 3];
#pragma unroll
        for (int m = 0; m < 16; ++m) {
            float4 w = *(const float4*)&Ws[(ng * 16 + m) * 64 + k];
            acc[m] += w.x * h0 + w.y * h1 + w.z * h2 + w.w * h3;
        }
    }
    size_t tg = (size_t)t * GB;
#pragma unroll
    for (int m = 0; m < 16; ++m) {
        int n = n0 + ng * 16 + m;
        g_xg0[tg + (size_t)n * BB + b] = acc[m] + bih[n] + bhh[n];
    }
}

// ================= K2: xg1 = h0 @ W_ih1^T + biases =================
__global__ void __launch_bounds__(256) k_xg1(const float* __restrict__ Wih,
                                             const float* __restrict__ bih,
                                             const float* __restrict__ bhh) {
    __shared__ float hs[64 * 32];
    __shared__ float Ws[64 * 64];
    const int tid = threadIdx.x, t = blockIdx.y, n0 = blockIdx.x * 64;
    const int b = tid & 31, ng = tid >> 5;
    float acc[8];
#pragma unroll
    for (int m = 0; m < 8; ++m) acc[m] = 0.f;
    for (int kc = 0; kc < HH; kc += 64) {
        for (int i = tid; i < 64 * 32; i += 256)
            hs[i] = g_h0[(size_t)t * HB + (size_t)kc * BB + i];
        for (int i = tid; i < 64 * 64; i += 256) {
            int r = i >> 6, k = i & 63;
            Ws[i] = Wih[(size_t)(n0 + r) * HH + kc + k];
        }
        __syncthreads();
        for (int k = 0; k < 64; k += 4) {
            float h0 = hs[(k + 0) * 32 + b], h1 = hs[(k + 1) * 32 + b];
            float h2 = hs[(k + 2) * 32 + b], h3 = hs[(k + 3) * 32 + b];
#pragma unroll
            for (int m = 0; m < 8; ++m) {
                float4 w = *(const float4*)&Ws[(ng * 8 + m) * 64 + k];
                acc[m] += w.x * h0 + w.y * h1 + w.z * h2 + w.w * h3;
            }
        }
        __syncthreads();
    }
    size_t tg = (size_t)t * GB;
#pragma unroll
    for (int m = 0; m < 8; ++m) {
        int n = n0 + ng * 8 + m;
        g_xg1[tg + (size_t)n * BB + b] = acc[m] + bih[n] + bhh[n];
    }
}

// ================= K3: dx1[t][k][b] = sum_n dg1[t][n][b] * W_ih1[n][k] =================
__global__ void __launch_bounds__(256) k_dx1(const float* __restrict__ Wih) {
    __shared__ float dgs[64 * 32];
    __shared__ float Ws[64 * 64];
    const int tid = threadIdx.x, t = blockIdx.y, kt0 = blockIdx.x * 64;
    const int b = tid & 31, kg = tid >> 5;
    float acc[8];
#pragma unroll
    for (int m = 0; m < 8; ++m) acc[m] = 0.f;
    for (int nb = 0; nb < GG; nb += 64) {
        for (int i = tid; i < 64 * 32; i += 256)
            dgs[i] = g_xg1[(size_t)t * GB + (size_t)nb * BB + i];
        for (int i = tid; i < 64 * 64; i += 256) {
            int r = i >> 6, k = i & 63;
            Ws[i] = Wih[(size_t)(nb + r) * HH + kt0 + k];
        }
        __syncthreads();
        for (int n = 0; n < 64; ++n) {
            float dgv = dgs[n * 32 + b];
            float4 wa = *(const float4*)&Ws[n * 64 + kg * 8];
            float4 wb = *(const float4*)&Ws[n * 64 + kg * 8 + 4];
            acc[0] += wa.x * dgv; acc[1] += wa.y * dgv;
            acc[2] += wa.z * dgv; acc[3] += wa.w * dgv;
            acc[4] += wb.x * dgv; acc[5] += wb.y * dgv;
            acc[6] += wb.z * dgv; acc[7] += wb.w * dgv;
        }
        __syncthreads();
    }
#pragma unroll
    for (int m = 0; m < 8; ++m)
        g_dx1[(size_t)t * HB + (size_t)(kt0 + kg * 8 + m) * BB + b] = acc[m];
}

// ================= K4: out[b][t][k] = sum_n dg0[t][n][b] * W_ih0[n][k], k<64 =================
__global__ void __launch_bounds__(256) k_dx(const float* __restrict__ Wih,
                                            float* __restrict__ out) {
    __shared__ float dgs[64 * 32];
    __shared__ float Ws[64 * 64];
    const int tid = threadIdx.x, t = blockIdx.x;
    const int b = tid & 31, kg = tid >> 5;
    float acc[8];
#pragma unroll
    for (int m = 0; m < 8; ++m) acc[m] = 0.f;
    for (int nb = 0; nb < GG; nb += 64) {
        for (int i = tid; i < 64 * 32; i += 256)
            dgs[i] = g_xg0[(size_t)t * GB + (size_t)nb * BB + i];
        for (int i = tid; i < 64 * 64; i += 256) {
            int r = i >> 6, k = i & 63;
            Ws[i] = Wih[(size_t)(nb + r) * NIN + k];
        }
        __syncthreads();
        for (int n = 0; n < 64; ++n) {
            float dgv = dgs[n * 32 + b];
            float4 wa = *(const float4*)&Ws[n * 64 + kg * 8];
            float4 wb = *(const float4*)&Ws[n * 64 + kg * 8 + 4];
            acc[0] += wa.x * dgv; acc[1] += wa.y * dgv;
            acc[2] += wa.z * dgv; acc[3] += wa.w * dgv;
            acc[4] += wb.x * dgv; acc[5] += wb.y * dgv;
            acc[6] += wb.z * dgv; acc[7] += wb.w * dgv;
        }
        __syncthreads();
    }
#pragma unroll
    for (int m = 0; m < 8; ++m)
        out[((size_t)b * TT + t) * NIN + kg * 8 + m] = acc[m];
}

// ================= persistent LSTM forward =================
// 128 CTAs; CTA owns 4 h-columns (j0..j0+3) -> 16 gate rows.
// dyn smem: sW[16][512] 32KB | sh[512][32] 64KB | sred[2][16][32] 4KB | sact[16][32] 2KB
#define FWD_SMEM ((16 * 512 + 512 * 32 + 1024 + 512) * 4)
__global__ void __launch_bounds__(256, 1) lstm_fwd_kernel(const float* __restrict__ Whh,
                                                          int layer) {
    extern __shared__ float smem[];
    float* sW = smem;
    float* sh = smem + 16 * 512;
    float* sred = sh + 512 * 32;
    float* sact = sred + 1024;

    float* gates = layer ? g_xg1 : g_xg0;
    float* cbuf = layer ? g_c1 : g_c0;
    float* hbuf = layer ? g_h1 : g_h0;

    const int tid = threadIdx.x, j0 = blockIdx.x * 4;
    const int b = tid & 31, wid = tid >> 5;
    const int rg = wid & 3, kh = wid >> 2;

    // sW[rho][k], rho = gate*4 + jl ; n = gate*HH + j0 + jl
    for (int i = tid; i < 16 * 512; i += 256) {
        int rho = i >> 9, k = i & 511;
        int n = (rho >> 2) * HH + j0 + (rho & 3);
        sW[i] = Whh[(size_t)n * HH + k];
    }
    unsigned gen0 = *((volatile unsigned*)&g_bar_gen);
    float creg = 0.f;
    __syncthreads();

    for (int t = 0; t < TT; ++t) {
        if (t == 0) {
            float4 z = make_float4(0.f, 0.f, 0.f, 0.f);
            for (int i = tid * 4; i < HB; i += 1024) *(float4*)&sh[i] = z;
        } else {
            const float* src = hbuf + (size_t)(t - 1) * HB;
            for (int i = tid * 4; i < HB; i += 1024)
                *(float4*)&sh[i] = *(const float4*)&src[i];
        }
        __syncthreads();

        float a0 = 0.f, a1 = 0.f, a2 = 0.f, a3 = 0.f;
        const float* w0p = sW + (rg * 4 + 0) * 512;
        const float* w1p = sW + (rg * 4 + 1) * 512;
        const float* w2p = sW + (rg * 4 + 2) * 512;
        const float* w3p = sW + (rg * 4 + 3) * 512;
        const int kb = kh * 256;
#pragma unroll 4
        for (int k = kb; k < kb + 256; k += 4) {
            float4 w0 = *(const float4*)(w0p + k);
            float4 w1 = *(const float4*)(w1p + k);
            float4 w2 = *(const float4*)(w2p + k);
            float4 w3 = *(const float4*)(w3p + k);
            float h0 = sh[(k + 0) * 32 + b], h1 = sh[(k + 1) * 32 + b];
            float h2 = sh[(k + 2) * 32 + b], h3 = sh[(k + 3) * 32 + b];
            a0 += w0.x * h0 + w0.y * h1 + w0.z * h2 + w0.w * h3;
            a1 += w1.x * h0 + w1.y * h1 + w1.z * h2 + w1.w * h3;
            a2 += w2.x * h0 + w2.y * h1 + w2.z * h2 + w2.w * h3;
            a3 += w3.x * h0 + w3.y * h1 + w3.z * h2 + w3.w * h3;
        }
        sred[kh * 512 + (rg * 4 + 0) * 32 + b] = a0;
        sred[kh * 512 + (rg * 4 + 1) * 32 + b] = a1;
        sred[kh * 512 + (rg * 4 + 2) * 32 + b] = a2;
        sred[kh * 512 + (rg * 4 + 3) * 32 + b] = a3;
        __syncthreads();

        size_t tg = (size_t)t * GB;
        for (int q = tid; q < 512; q += 256) {
            int rho = q >> 5, bb = q & 31;
            int n = (rho >> 2) * HH + j0 + (rho & 3);
            float g = sred[q] + sred[512 + q] + gates[tg + (size_t)n * BB + bb];
            float v = (rho >= 8 && rho < 12) ? tanhf(g) : sigf(g);
            sact[q] = v;
            gates[tg + (size_t)n * BB + bb] = v;
        }
        __syncthreads();

        if (tid < 128) {
            int jl = tid >> 5, bb = tid & 31;
            float iv = sact[(0 + jl) * 32 + bb];
            float fv = sact[(4 + jl) * 32 + bb];
            float gv = sact[(8 + jl) * 32 + bb];
            float ov = sact[(12 + jl) * 32 + bb];
            float c = fv * creg + iv * gv;
            creg = c;
            size_t o = (size_t)t * HB + (size_t)(j0 + jl) * BB + bb;
            cbuf[o] = c;
            hbuf[o] = ov * tanhf(c);
        }
        grid_barrier(gen0 + (unsigned)(t + 1));
    }
}

// ================= persistent LSTM backward (BPTT) =================
// CTA owns 8 j (j0..j0+7) x 16 b (b0..b0+15). dg written in place over gates.
// dyn smem: sWc[2048][8] 64KB | sdg[512][16] 32KB | sred[8][8][16] 4KB
#define BWD_SMEM ((2048 * 8 + 512 * 16 + 1024) * 4)
__global__ void __launch_bounds__(256, 1) lstm_bwd_kernel(const float* __restrict__ Whh,
                                                          const float* __restrict__ Wout,
                                                          int layer) {
    extern __shared__ float smem[];
    float* sWc = smem;
    float* sdg = smem + 2048 * 8;
    float* sred = sdg + 512 * 16;

    float* gates = layer ? g_xg1 : g_xg0;
    const float* cbuf = layer ? g_c1 : g_c0;

    const int tid = threadIdx.x;
    const int j0 = (blockIdx.x >> 1) * 8;
    const int b0 = (blockIdx.x & 1) * 16;
    const int half8 = tid >> 5, jg = (tid >> 4) & 1, bl = tid & 15;
    const int cjj = tid >> 4, cbl = tid & 15;   // phase-C mapping (tid<128)

    // sWc[n][jj] = Whh[n][j0+jj]
    for (int i = tid; i < 2048 * 2; i += 256) {
        int n = i >> 1, q = i & 1;
        *(float4*)&sWc[n * 8 + q * 4] = *(const float4*)&Whh[(size_t)n * HH + j0 + q * 4];
    }
    unsigned gen0 = *((volatile unsigned*)&g_bar_gen);
    float dcreg = 0.f;
    float dho_c = 0.f;
    if (layer == 1 && tid < 128) dho_c = Wout[j0 + cjj];
    __syncthreads();

    for (int t = TT - 1; t >= 0; --t) {
        float a0 = 0.f, a1 = 0.f, a2 = 0.f, a3 = 0.f;
        if (t < TT - 1) {
            const float* dgp = gates + (size_t)(t + 1) * GB;
            for (int cc = 0; cc < 4; ++cc) {
                int nb = cc * 512;
                for (int f4 = tid; f4 < 512 * 4; f4 += 256) {
                    int nl = f4 >> 2, bq = f4 & 3;
                    *(float4*)&sdg[nl * 16 + bq * 4] =
                        *(const float4*)&dgp[(size_t)(nb + nl) * BB + b0 + bq * 4];
                }
                __syncthreads();
                int n0l = half8 * 64;
#pragma unroll 4
                for (int nl = n0l; nl < n0l + 64; ++nl) {
                    float dgv = sdg[nl * 16 + bl];
                    float4 w = *(const float4*)&sWc[(nb + nl) * 8 + jg * 4];
                    a0 += w.x * dgv; a1 += w.y * dgv; a2 += w.z * dgv; a3 += w.w * dgv;
                }
                __syncthreads();
            }
        }
        sred[(half8 * 8 + jg * 4 + 0) * 16 + bl] = a0;
        sred[(half8 * 8 + jg * 4 + 1) * 16 + bl] = a1;
        sred[(half8 * 8 + jg * 4 + 2) * 16 + bl] = a2;
        sred[(half8 * 8 + jg * 4 + 3) * 16 + bl] = a3;
        __syncthreads();

        if (tid < 128) {
            float dhrec = 0.f;
#pragma unroll
            for (int h = 0; h < 8; ++h) dhrec += sred[(h * 8 + cjj) * 16 + cbl];
            int j = j0 + cjj, b = b0 + cbl;
            size_t gb = (size_t)t * GB + (size_t)j * BB + b;
            float iv = gates[gb];
            float fv = gates[gb + (size_t)512 * BB];
            float gv = gates[gb + (size_t)1024 * BB];
            float ov = gates[gb + (size_t)1536 * BB];
            size_t co = (size_t)t * HB + (size_t)j * BB + b;
            float c = cbuf[co];
            float cprev = (t > 0) ? cbuf[co - HB] : 0.f;
            float dho = (layer == 1) ? dho_c : g_dx1[co];
            float dh = dho + dhrec;
            float tc = tanhf(c);
            float dc = dcreg + dh * ov * (1.f - tc * tc);
            float dgi = (dc * gv) * iv * (1.f - iv);
            float dgf = (dc * cprev) * fv * (1.f - fv);
            float dgg = (dc * iv) * (1.f - gv * gv);
            float dgo = (dh * tc) * ov * (1.f - ov);
            dcreg = dc * fv;
            gates[gb] = dgi;
            gates[gb + (size_t)512 * BB] = dgf;
            gates[gb + (size_t)1024 * BB] = dgg;
            gates[gb + (size_t)1536 * BB] = dgo;
        }
        grid_barrier(gen0 + (unsigned)(TT - t));
    }
}

extern "C" void kernel_launch(void* const* d_in, const int* in_sizes, int n_in,
                              void* d_out, int out_size) {
    const float* x    = (const float*)d_in[0];
    const float* Wih0 = (const float*)d_in[1];
    const float* Whh0 = (const float*)d_in[2];
    const float* bih0 = (const float*)d_in[3];
    const float* bhh0 = (const float*)d_in[4];
    const float* Wih1 = (const float*)d_in[5];
    const float* Whh1 = (const float*)d_in[6];
    const float* bih1 = (const float*)d_in[7];
    const float* bhh1 = (const float*)d_in[8];
    const float* Wout = (const float*)d_in[9];
    float* out = (float*)d_out;

    cudaFuncSetAttribute(lstm_fwd_kernel, cudaFuncAttributeMaxDynamicSharedMemorySize, FWD_SMEM);
    cudaFuncSetAttribute(lstm_bwd_kernel, cudaFuncAttributeMaxDynamicSharedMemorySize, BWD_SMEM);

    k_xg0<<<dim3(16, 512), 256>>>(x, Wih0, bih0, bhh0);
    lstm_fwd_kernel<<<NB, 256, FWD_SMEM>>>(Whh0, 0);
    k_xg1<<<dim3(32, 512), 256>>>(Wih1, bih1, bhh1);
    lstm_fwd_kernel<<<NB, 256, FWD_SMEM>>>(Whh1, 1);
    lstm_bwd_kernel<<<NB, 256, BWD_SMEM>>>(Whh1, Wout, 1);
    k_dx1<<<dim3(8, 512), 256>>>(Wih1);
    lstm_bwd_kernel<<<NB, 256, BWD_SMEM>>>(Whh0, Wout, 0);
    k_dx<<<512, 256>>>(Wih0, out);
}

// round 13
// speedup vs baseline: 1.0346x; 1.0346x over previous
#include <cuda_runtime.h>
#include <math.h>

#define TT 512
#define BB 32
#define HH 512
#define GG 2048
#define NIN 64
#define NB 128
#define HB 16384   // HH*BB
#define GB 65536   // GG*BB

typedef unsigned long long u64;

// ---- static device scratch (no allocations allowed) ----
__device__ float g_xg0[(size_t)TT * GB];   // xg0 -> activated gates L0 -> dg0 (in place)
__device__ float g_xg1[(size_t)TT * GB];
__device__ float g_c0[(size_t)TT * HB];
__device__ float g_c1[(size_t)TT * HB];
__device__ float g_h0[(size_t)TT * HB];    // [t][k][b]  (layer0 h, consumed by k_xg1)
__device__ float g_hT[(size_t)TT * HB];    // [t][b][j]  (transposed h for fwd staging; reused by both layers)
__device__ float g_dx1[(size_t)TT * HB];   // dL/d(h0) from layer1 input path, [t][j][b]

__device__ unsigned g_bar_count = 0;
__device__ unsigned g_bar_gen   = 0;

__device__ __forceinline__ void grid_barrier(unsigned target) {
    __syncthreads();
    if (threadIdx.x == 0) {
        __threadfence();
        unsigned old = atomicAdd(&g_bar_count, 1u);
        if (old == NB - 1) {
            g_bar_count = 0;
            __threadfence();
            atomicExch(&g_bar_gen, target);
        } else {
            while ((int)(*(volatile unsigned*)&g_bar_gen - target) < 0) {}
            __threadfence();
        }
    }
    __syncthreads();
}

__device__ __forceinline__ float sigf(float x) { return 1.0f / (1.0f + expf(-x)); }

// ---- packed fp32x2 helpers (Blackwell FFMA2) ----
__device__ __forceinline__ u64 pack2(float x, float y) {
    u64 r; asm("mov.b64 %0, {%1, %2};" : "=l"(r) : "f"(x), "f"(y)); return r;
}
__device__ __forceinline__ void unpack2(u64 v, float& x, float& y) {
    asm("mov.b64 {%0, %1}, %2;" : "=f"(x), "=f"(y) : "l"(v));
}
__device__ __forceinline__ u64 ffma2(u64 a, u64 b, u64 c) {
    u64 d; asm("fma.rn.f32x2 %0, %1, %2, %3;" : "=l"(d) : "l"(a), "l"(b), "l"(c)); return d;
}

// ================= K1: xg0 = x @ W_ih0^T + b_ih0 + b_hh0, layout [t][n][b] =================
__global__ void __launch_bounds__(256) k_xg0(const float* __restrict__ x,
                                             const float* __restrict__ Wih,
                                             const float* __restrict__ bih,
                                             const float* __restrict__ bhh) {
    __shared__ float xs[32 * 65];
    __shared__ float Ws[128 * 64];
    const int tid = threadIdx.x, t = blockIdx.y, n0 = blockIdx.x * 128;
    for (int i = tid; i < 32 * 64; i += 256) {
        int b = i >> 6, k = i & 63;
        xs[b * 65 + k] = x[((size_t)b * TT + t) * NIN + k];
    }
    for (int i = tid; i < 128 * 64; i += 256) {
        int r = i >> 6, k = i & 63;
        Ws[i] = Wih[(size_t)(n0 + r) * NIN + k];
    }
    __syncthreads();
    const int b = tid & 31, ng = tid >> 5;
    u64 acc[16];
#pragma unroll
    for (int m = 0; m < 16; ++m) acc[m] = 0ull;
    for (int k = 0; k < 64; k += 4) {
        u64 hp01 = pack2(xs[b * 65 + k], xs[b * 65 + k + 1]);
        u64 hp23 = pack2(xs[b * 65 + k + 2], xs[b * 65 + k + 3]);
#pragma unroll
        for (int m = 0; m < 16; ++m) {
            ulonglong2 wp = *(const ulonglong2*)&Ws[(ng * 16 + m) * 64 + k];
            acc[m] = ffma2(wp.x, hp01, acc[m]);
            acc[m] = ffma2(wp.y, hp23, acc[m]);
        }
    }
    size_t tg = (size_t)t * GB;
#pragma unroll
    for (int m = 0; m < 16; ++m) {
        int n = n0 + ng * 16 + m;
        float lo, hi; unpack2(acc[m], lo, hi);
        g_xg0[tg + (size_t)n * BB + b] = lo + hi + bih[n] + bhh[n];
    }
}

// ================= K2: xg1 = h0 @ W_ih1^T + biases =================
__global__ void __launch_bounds__(256) k_xg1(const float* __restrict__ Wih,
                                             const float* __restrict__ bih,
                                             const float* __restrict__ bhh) {
    __shared__ float hs[64 * 32];
    __shared__ float Ws[64 * 64];
    const int tid = threadIdx.x, t = blockIdx.y, n0 = blockIdx.x * 64;
    const int b = tid & 31, ng = tid >> 5;
    u64 acc[8];
#pragma unroll
    for (int m = 0; m < 8; ++m) acc[m] = 0ull;
    for (int kc = 0; kc < HH; kc += 64) {
        for (int i = tid; i < 64 * 32; i += 256)
            hs[i] = g_h0[(size_t)t * HB + (size_t)kc * BB + i];
        for (int i = tid; i < 64 * 64; i += 256) {
            int r = i >> 6, k = i & 63;
            Ws[i] = Wih[(size_t)(n0 + r) * HH + kc + k];
        }
        __syncthreads();
        for (int k = 0; k < 64; k += 4) {
            u64 hp01 = pack2(hs[(k + 0) * 32 + b], hs[(k + 1) * 32 + b]);
            u64 hp23 = pack2(hs[(k + 2) * 32 + b], hs[(k + 3) * 32 + b]);
#pragma unroll
            for (int m = 0; m < 8; ++m) {
                ulonglong2 wp = *(const ulonglong2*)&Ws[(ng * 8 + m) * 64 + k];
                acc[m] = ffma2(wp.x, hp01, acc[m]);
                acc[m] = ffma2(wp.y, hp23, acc[m]);
            }
        }
        __syncthreads();
    }
    size_t tg = (size_t)t * GB;
#pragma unroll
    for (int m = 0; m < 8; ++m) {
        int n = n0 + ng * 8 + m;
        float lo, hi; unpack2(acc[m], lo, hi);
        g_xg1[tg + (size_t)n * BB + b] = lo + hi + bih[n] + bhh[n];
    }
}

// ================= K3: dx1[t][k][b] = sum_n dg1[t][n][b] * W_ih1[n][k] =================
__global__ void __launch_bounds__(256) k_dx1(const float* __restrict__ Wih) {
    __shared__ float dgs[64 * 32];
    __shared__ float Ws[64 * 64];
    const int tid = threadIdx.x, t = blockIdx.y, kt0 = blockIdx.x * 64;
    const int b = tid & 31, kg = tid >> 5;
    u64 acc[4];   // pairs across output k: (m0,m1)(m2,m3)(m4,m5)(m6,m7)
#pragma unroll
    for (int m = 0; m < 4; ++m) acc[m] = 0ull;
    for (int nb = 0; nb < GG; nb += 64) {
        for (int i = tid; i < 64 * 32; i += 256)
            dgs[i] = g_xg1[(size_t)t * GB + (size_t)nb * BB + i];
        for (int i = tid; i < 64 * 64; i += 256) {
            int r = i >> 6, k = i & 63;
            Ws[i] = Wih[(size_t)(nb + r) * HH + kt0 + k];
        }
        __syncthreads();
        for (int n = 0; n < 64; ++n) {
            u64 dpp = pack2(dgs[n * 32 + b], dgs[n * 32 + b]);
            ulonglong2 wa = *(const ulonglong2*)&Ws[n * 64 + kg * 8];
            ulonglong2 wb = *(const ulonglong2*)&Ws[n * 64 + kg * 8 + 4];
            acc[0] = ffma2(wa.x, dpp, acc[0]);
            acc[1] = ffma2(wa.y, dpp, acc[1]);
            acc[2] = ffma2(wb.x, dpp, acc[2]);
            acc[3] = ffma2(wb.y, dpp, acc[3]);
        }
        __syncthreads();
    }
#pragma unroll
    for (int p = 0; p < 4; ++p) {
        float lo, hi; unpack2(acc[p], lo, hi);
        g_dx1[(size_t)t * HB + (size_t)(kt0 + kg * 8 + 2 * p) * BB + b] = lo;
        g_dx1[(size_t)t * HB + (size_t)(kt0 + kg * 8 + 2 * p + 1) * BB + b] = hi;
    }
}

// ================= K4: out[b][t][k] = sum_n dg0[t][n][b] * W_ih0[n][k], k<64 =================
__global__ void __launch_bounds__(256) k_dx(const float* __restrict__ Wih,
                                            float* __restrict__ out) {
    __shared__ float dgs[64 * 32];
    __shared__ float Ws[64 * 64];
    const int tid = threadIdx.x, t = blockIdx.x;
    const int b = tid & 31, kg = tid >> 5;
    u64 acc[4];
#pragma unroll
    for (int m = 0; m < 4; ++m) acc[m] = 0ull;
    for (int nb = 0; nb < GG; nb += 64) {
        for (int i = tid; i < 64 * 32; i += 256)
            dgs[i] = g_xg0[(size_t)t * GB + (size_t)nb * BB + i];
        for (int i = tid; i < 64 * 64; i += 256) {
            int r = i >> 6, k = i & 63;
            Ws[i] = Wih[(size_t)(nb + r) * NIN + k];
        }
        __syncthreads();
        for (int n = 0; n < 64; ++n) {
            u64 dpp = pack2(dgs[n * 32 + b], dgs[n * 32 + b]);
            ulonglong2 wa = *(const ulonglong2*)&Ws[n * 64 + kg * 8];
            ulonglong2 wb = *(const ulonglong2*)&Ws[n * 64 + kg * 8 + 4];
            acc[0] = ffma2(wa.x, dpp, acc[0]);
            acc[1] = ffma2(wa.y, dpp, acc[1]);
            acc[2] = ffma2(wb.x, dpp, acc[2]);
            acc[3] = ffma2(wb.y, dpp, acc[3]);
        }
        __syncthreads();
    }
#pragma unroll
    for (int p = 0; p < 4; ++p) {
        float lo, hi; unpack2(acc[p], lo, hi);
        out[((size_t)b * TT + t) * NIN + kg * 8 + 2 * p] = lo;
        out[((size_t)b * TT + t) * NIN + kg * 8 + 2 * p + 1] = hi;
    }
}

// ================= persistent LSTM forward =================
// 128 CTAs; CTA owns 4 h-columns (j0..j0+3) -> 16 gate rows.
// smem: sW[16][512] 32KB | sh2[32][514] ~64KB | sred[2][16][32] 4KB | sact[16][32] 2KB
#define SH2_STRIDE 514
#define FWD_SMEM ((16 * 512 + 32 * SH2_STRIDE + 1024 + 512) * 4)
__global__ void __launch_bounds__(256, 1) lstm_fwd_kernel(const float* __restrict__ Whh,
                                                          int layer) {
    extern __shared__ float smem[];
    float* sW = smem;                            // 8192 floats
    float* sh2 = smem + 16 * 512;                // 32*514 floats, layout [b][k] stride 514
    float* sred = sh2 + 32 * SH2_STRIDE;         // 1024
    float* sact = sred + 1024;                   // 512

    float* gates = layer ? g_xg1 : g_xg0;
    float* cbuf = layer ? g_c1 : g_c0;

    const int tid = threadIdx.x, j0 = blockIdx.x * 4;
    const int b = tid & 31, wid = tid >> 5;
    const int rg = wid & 3, kh = wid >> 2;

    // sW[rho][k], rho = gate*4 + jl ; n = gate*HH + j0 + jl
    for (int i = tid; i < 16 * 512; i += 256) {
        int rho = i >> 9, k = i & 511;
        int n = (rho >> 2) * HH + j0 + (rho & 3);
        sW[i] = Whh[(size_t)n * HH + k];
    }
    unsigned gen0 = *((volatile unsigned*)&g_bar_gen);
    float creg = 0.f;
    __syncthreads();

    for (int t = 0; t < TT; ++t) {
        // stage h_{t-1} transposed into sh2[b][k]
        if (t == 0) {
            for (int i = tid; i < 32 * SH2_STRIDE / 2; i += 256)
                ((u64*)sh2)[i] = 0ull;
        } else {
            const float* src = g_hT + (size_t)(t - 1) * HB;   // [b][j]
#pragma unroll
            for (int r = 0; r < 16; ++r) {
                int i4 = tid + r * 256;
                float4 v = *(const float4*)&src[i4 * 4];
                int bb = i4 >> 7;            // 128 float4 per b-row
                int k = (i4 & 127) * 4;
                float* dst = &sh2[bb * SH2_STRIDE + k];
                *(float2*)dst = make_float2(v.x, v.y);
                *(float2*)(dst + 2) = make_float2(v.z, v.w);
            }
        }
        __syncthreads();

        // packed matmul: 4 rows (rg), k half (kh), lane b
        u64 acc0 = 0ull, acc1 = 0ull, acc2 = 0ull, acc3 = 0ull;
        const float* w0p = sW + (rg * 4 + 0) * 512;
        const float* w1p = sW + (rg * 4 + 1) * 512;
        const float* w2p = sW + (rg * 4 + 2) * 512;
        const float* w3p = sW + (rg * 4 + 3) * 512;
        const float* hp = sh2 + b * SH2_STRIDE;
        const int kb = kh * 256;
#pragma unroll 4
        for (int k = kb; k < kb + 256; k += 4) {
            u64 h01 = *(const u64*)(hp + k);
            u64 h23 = *(const u64*)(hp + k + 2);
            ulonglong2 w0 = *(const ulonglong2*)(w0p + k);
            ulonglong2 w1 = *(const ulonglong2*)(w1p + k);
            ulonglong2 w2 = *(const ulonglong2*)(w2p + k);
            ulonglong2 w3 = *(const ulonglong2*)(w3p + k);
            acc0 = ffma2(w0.x, h01, acc0); acc0 = ffma2(w0.y, h23, acc0);
            acc1 = ffma2(w1.x, h01, acc1); acc1 = ffma2(w1.y, h23, acc1);
            acc2 = ffma2(w2.x, h01, acc2); acc2 = ffma2(w2.y, h23, acc2);
            acc3 = ffma2(w3.x, h01, acc3); acc3 = ffma2(w3.y, h23, acc3);
        }
        float lo, hi;
        unpack2(acc0, lo, hi); sred[kh * 512 + (rg * 4 + 0) * 32 + b] = lo + hi;
        unpack2(acc1, lo, hi); sred[kh * 512 + (rg * 4 + 1) * 32 + b] = lo + hi;
        unpack2(acc2, lo, hi); sred[kh * 512 + (rg * 4 + 2) * 32 + b] = lo + hi;
        unpack2(acc3, lo, hi); sred[kh * 512 + (rg * 4 + 3) * 32 + b] = lo + hi;
        __syncthreads();

        size_t tg = (size_t)t * GB;
        for (int q = tid; q < 512; q += 256) {
            int rho = q >> 5, bb = q & 31;
            int n = (rho >> 2) * HH + j0 + (rho & 3);
            float g = sred[q] + sred[512 + q] + gates[tg + (size_t)n * BB + bb];
            float v = (rho >= 8 && rho < 12) ? tanhf(g) : sigf(g);
            sact[q] = v;
            gates[tg + (size_t)n * BB + bb] = v;
        }
        __syncthreads();

        if (tid < 128) {
            int jl = tid >> 5, bb = tid & 31;
            float iv = sact[(0 + jl) * 32 + bb];
            float fv = sact[(4 + jl) * 32 + bb];
            float gv = sact[(8 + jl) * 32 + bb];
            float ov = sact[(12 + jl) * 32 + bb];
            float c = fv * creg + iv * gv;
            creg = c;
            float h = ov * tanhf(c);
            int j = j0 + jl;
            cbuf[(size_t)t * HB + (size_t)j * BB + bb] = c;
            g_hT[(size_t)t * HB + (size_t)bb * HH + j] = h;
            if (layer == 0)
                g_h0[(size_t)t * HB + (size_t)j * BB + bb] = h;
        }
        grid_barrier(gen0 + (unsigned)(t + 1));
    }
}

// ================= persistent LSTM backward (BPTT) =================
// CTA owns 8 j (j0..j0+7) x 16 b. dg written in place over gates.
// smem: sWc[2048][8] 64KB | sdg[512][16] 32KB | sred[8][8][16] 4KB
#define BWD_SMEM ((2048 * 8 + 512 * 16 + 1024) * 4)
__global__ void __launch_bounds__(256, 1) lstm_bwd_kernel(const float* __restrict__ Whh,
                                                          const float* __restrict__ Wout,
                                                          int layer) {
    extern __shared__ float smem[];
    float* sWc = smem;
    float* sdg = smem + 2048 * 8;
    float* sred = sdg + 512 * 16;

    float* gates = layer ? g_xg1 : g_xg0;
    const float* cbuf = layer ? g_c1 : g_c0;

    const int tid = threadIdx.x;
    const int j0 = (blockIdx.x >> 1) * 8;
    const int b0 = (blockIdx.x & 1) * 16;
    const int half8 = tid >> 5, jg = (tid >> 4) & 1, bl = tid & 15;
    const int cjj = tid >> 4, cbl = tid & 15;   // phase-C mapping (tid<128)

    for (int i = tid; i < 2048 * 2; i += 256) {
        int n = i >> 1, q = i & 1;
        *(float4*)&sWc[n * 8 + q * 4] = *(const float4*)&Whh[(size_t)n * HH + j0 + q * 4];
    }
    unsigned gen0 = *((volatile unsigned*)&g_bar_gen);
    float dcreg = 0.f;
    float dho_c = 0.f;
    if (layer == 1 && tid < 128) dho_c = Wout[j0 + cjj];
    __syncthreads();

    for (int t = TT - 1; t >= 0; --t) {
        u64 accA = 0ull, accB = 0ull;   // (jg*4+0, +1) and (+2, +3)
        if (t < TT - 1) {
            const float* dgp = gates + (size_t)(t + 1) * GB;
            for (int cc = 0; cc < 4; ++cc) {
                int nb = cc * 512;
                for (int f4 = tid; f4 < 512 * 4; f4 += 256) {
                    int nl = f4 >> 2, bq = f4 & 3;
                    *(float4*)&sdg[nl * 16 + bq * 4] =
                        *(const float4*)&dgp[(size_t)(nb + nl) * BB + b0 + bq * 4];
                }
                __syncthreads();
                int n0l = half8 * 64;
#pragma unroll 4
                for (int nl = n0l; nl < n0l + 64; ++nl) {
                    float dgv = sdg[nl * 16 + bl];
                    u64 dpp = pack2(dgv, dgv);
                    ulonglong2 wp = *(const ulonglong2*)&sWc[(nb + nl) * 8 + jg * 4];
                    accA = ffma2(wp.x, dpp, accA);
                    accB = ffma2(wp.y, dpp, accB);
                }
                __syncthreads();
            }
        }
        {
            float lo, hi;
            unpack2(accA, lo, hi);
            sred[(half8 * 8 + jg * 4 + 0) * 16 + bl] = lo;
            sred[(half8 * 8 + jg * 4 + 1) * 16 + bl] = hi;
            unpack2(accB, lo, hi);
            sred[(half8 * 8 + jg * 4 + 2) * 16 + bl] = lo;
            sred[(half8 * 8 + jg * 4 + 3) * 16 + bl] = hi;
        }
        __syncthreads();

        if (tid < 128) {
            float dhrec = 0.f;
#pragma unroll
            for (int h = 0; h < 8; ++h) dhrec += sred[(h * 8 + cjj) * 16 + cbl];
            int j = j0 + cjj, b = b0 + cbl;
            size_t gb = (size_t)t * GB + (size_t)j * BB + b;
            float iv = gates[gb];
            float fv = gates[gb + (size_t)512 * BB];
            float gv = gates[gb + (size_t)1024 * BB];
            float ov = gates[gb + (size_t)1536 * BB];
            size_t co = (size_t)t * HB + (size_t)j * BB + b;
            float c = cbuf[co];
            float cprev = (t > 0) ? cbuf[co - HB] : 0.f;
            float dho = (layer == 1) ? dho_c : g_dx1[co];
            float dh = dho + dhrec;
            float tc = tanhf(c);
            float dc = dcreg + dh * ov * (1.f - tc * tc);
            float dgi = (dc * gv) * iv * (1.f - iv);
            float dgf = (dc * cprev) * fv * (1.f - fv);
            float dgg = (dc * iv) * (1.f - gv * gv);
            float dgo = (dh * tc) * ov * (1.f - ov);
            dcreg = dc * fv;
            gates[gb] = dgi;
            gates[gb + (size_t)512 * BB] = dgf;
            gates[gb + (size_t)1024 * BB] = dgg;
            gates[gb + (size_t)1536 * BB] = dgo;
        }
        grid_barrier(gen0 + (unsigned)(TT - t));
    }
}

extern "C" void kernel_launch(void* const* d_in, const int* in_sizes, int n_in,
                              void* d_out, int out_size) {
    const float* x    = (const float*)d_in[0];
    const float* Wih0 = (const float*)d_in[1];
    const float* Whh0 = (const float*)d_in[2];
    const float* bih0 = (const float*)d_in[3];
    const float* bhh0 = (const float*)d_in[4];
    const float* Wih1 = (const float*)d_in[5];
    const float* Whh1 = (const float*)d_in[6];
    const float* bih1 = (const float*)d_in[7];
    const float* bhh1 = (const float*)d_in[8];
    const float* Wout = (const float*)d_in[9];
    float* out = (float*)d_out;

    cudaFuncSetAttribute(lstm_fwd_kernel, cudaFuncAttributeMaxDynamicSharedMemorySize, FWD_SMEM);
    cudaFuncSetAttribute(lstm_bwd_kernel, cudaFuncAttributeMaxDynamicSharedMemorySize, BWD_SMEM);

    k_xg0<<<dim3(16, 512), 256>>>(x, Wih0, bih0, bhh0);
    lstm_fwd_kernel<<<NB, 256, FWD_SMEM>>>(Whh0, 0);
    k_xg1<<<dim3(32, 512), 256>>>(Wih1, bih1, bhh1);
    lstm_fwd_kernel<<<NB, 256, FWD_SMEM>>>(Whh1, 1);
    lstm_bwd_kernel<<<NB, 256, BWD_SMEM>>>(Whh1, Wout, 1);
    k_dx1<<<dim3(8, 512), 256>>>(Wih1);
    lstm_bwd_kernel<<<NB, 256, BWD_SMEM>>>(Whh0, Wout, 0);
    k_dx<<<512, 256>>>(Wih0, out);
}

// round 14
// speedup vs baseline: 1.1757x; 1.1364x over previous
#include <cuda_runtime.h>
#include <math.h>

#define TT 512
#define BB 32
#define HH 512
#define GG 2048
#define NIN 64
#define NB 128
#define HB 16384   // HH*BB
#define GB 65536   // GG*BB

typedef unsigned long long u64;

// ---- static device scratch (no allocations allowed) ----
__device__ float g_xg0[(size_t)TT * GB];   // xg0 -> activated gates L0 -> dg0 (in place)
__device__ float g_xg1[(size_t)TT * GB];
__device__ float g_c0[(size_t)TT * HB];
__device__ float g_c1[(size_t)TT * HB];
__device__ float g_h0[(size_t)TT * HB];    // [t][k][b]  (layer0 h, consumed by k_xg1)
__device__ float g_hT[(size_t)TT * HB];    // [t][b][j]  (transposed h for fwd staging)
__device__ float g_dx1[(size_t)TT * HB];   // dL/d(h0) from layer1 input path, [t][j][b]

__device__ unsigned g_bar_count = 0;
__device__ unsigned g_bar_gen   = 0;

__device__ __forceinline__ void grid_barrier(unsigned target) {
    __syncthreads();
    if (threadIdx.x == 0) {
        __threadfence();
        unsigned old = atomicAdd(&g_bar_count, 1u);
        if (old == NB - 1) {
            g_bar_count = 0;
            __threadfence();
            atomicExch(&g_bar_gen, target);
        } else {
            while ((int)(*(volatile unsigned*)&g_bar_gen - target) < 0) {}
            __threadfence();
        }
    }
    __syncthreads();
}

__device__ __forceinline__ float sigf(float x) { return 1.0f / (1.0f + expf(-x)); }

// ---- packed fp32x2 helpers ----
__device__ __forceinline__ u64 pack2(float x, float y) {
    u64 r; asm("mov.b64 %0, {%1, %2};" : "=l"(r) : "f"(x), "f"(y)); return r;
}
__device__ __forceinline__ void unpack2(u64 v, float& x, float& y) {
    asm("mov.b64 {%0, %1}, %2;" : "=f"(x), "=f"(y) : "l"(v));
}
__device__ __forceinline__ u64 ffma2(u64 a, u64 b, u64 c) {
    u64 d; asm("fma.rn.f32x2 %0, %1, %2, %3;" : "=l"(d) : "l"(a), "l"(b), "l"(c)); return d;
}

// ================= K1: xg0 = x @ W_ih0^T + b_ih0 + b_hh0, layout [t][n][b] =================
__global__ void __launch_bounds__(256) k_xg0(const float* __restrict__ x,
                                             const float* __restrict__ Wih,
                                             const float* __restrict__ bih,
                                             const float* __restrict__ bhh) {
    __shared__ float xs[32 * 65];
    __shared__ float Ws[128 * 64];
    const int tid = threadIdx.x, t = blockIdx.y, n0 = blockIdx.x * 128;
    for (int i = tid; i < 32 * 64; i += 256) {
        int b = i >> 6, k = i & 63;
        xs[b * 65 + k] = x[((size_t)b * TT + t) * NIN + k];
    }
    for (int i = tid; i < 128 * 64; i += 256) {
        int r = i >> 6, k = i & 63;
        Ws[i] = Wih[(size_t)(n0 + r) * NIN + k];
    }
    __syncthreads();
    const int b = tid & 31, ng = tid >> 5;
    u64 acc[16];
#pragma unroll
    for (int m = 0; m < 16; ++m) acc[m] = 0ull;
    for (int k = 0; k < 64; k += 4) {
        u64 hp01 = pack2(xs[b * 65 + k], xs[b * 65 + k + 1]);
        u64 hp23 = pack2(xs[b * 65 + k + 2], xs[b * 65 + k + 3]);
#pragma unroll
        for (int m = 0; m < 16; ++m) {
            ulonglong2 wp = *(const ulonglong2*)&Ws[(ng * 16 + m) * 64 + k];
            acc[m] = ffma2(wp.x, hp01, acc[m]);
            acc[m] = ffma2(wp.y, hp23, acc[m]);
        }
    }
    size_t tg = (size_t)t * GB;
#pragma unroll
    for (int m = 0; m < 16; ++m) {
        int n = n0 + ng * 16 + m;
        float lo, hi; unpack2(acc[m], lo, hi);
        g_xg0[tg + (size_t)n * BB + b] = lo + hi + bih[n] + bhh[n];
    }
}

// ================= K2: xg1 = h0 @ W_ih1^T + biases =================
__global__ void __launch_bounds__(256) k_xg1(const float* __restrict__ Wih,
                                             const float* __restrict__ bih,
                                             const float* __restrict__ bhh) {
    __shared__ float hs[64 * 32];
    __shared__ float Ws[64 * 64];
    const int tid = threadIdx.x, t = blockIdx.y, n0 = blockIdx.x * 64;
    const int b = tid & 31, ng = tid >> 5;
    u64 acc[8];
#pragma unroll
    for (int m = 0; m < 8; ++m) acc[m] = 0ull;
    for (int kc = 0; kc < HH; kc += 64) {
        for (int i = tid; i < 64 * 32; i += 256)
            hs[i] = g_h0[(size_t)t * HB + (size_t)kc * BB + i];
        for (int i = tid; i < 64 * 64; i += 256) {
            int r = i >> 6, k = i & 63;
            Ws[i] = Wih[(size_t)(n0 + r) * HH + kc + k];
        }
        __syncthreads();
        for (int k = 0; k < 64; k += 4) {
            u64 hp01 = pack2(hs[(k + 0) * 32 + b], hs[(k + 1) * 32 + b]);
            u64 hp23 = pack2(hs[(k + 2) * 32 + b], hs[(k + 3) * 32 + b]);
#pragma unroll
            for (int m = 0; m < 8; ++m) {
                ulonglong2 wp = *(const ulonglong2*)&Ws[(ng * 8 + m) * 64 + k];
                acc[m] = ffma2(wp.x, hp01, acc[m]);
                acc[m] = ffma2(wp.y, hp23, acc[m]);
            }
        }
        __syncthreads();
    }
    size_t tg = (size_t)t * GB;
#pragma unroll
    for (int m = 0; m < 8; ++m) {
        int n = n0 + ng * 8 + m;
        float lo, hi; unpack2(acc[m], lo, hi);
        g_xg1[tg + (size_t)n * BB + b] = lo + hi + bih[n] + bhh[n];
    }
}

// ================= K3: dx1[t][k][b] = sum_n dg1[t][n][b] * W_ih1[n][k] =================
__global__ void __launch_bounds__(256) k_dx1(const float* __restrict__ Wih) {
    __shared__ float dgs[64 * 32];
    __shared__ float Ws[64 * 64];
    const int tid = threadIdx.x, t = blockIdx.y, kt0 = blockIdx.x * 64;
    const int b = tid & 31, kg = tid >> 5;
    u64 acc[4];
#pragma unroll
    for (int m = 0; m < 4; ++m) acc[m] = 0ull;
    for (int nb = 0; nb < GG; nb += 64) {
        for (int i = tid; i < 64 * 32; i += 256)
            dgs[i] = g_xg1[(size_t)t * GB + (size_t)nb * BB + i];
        for (int i = tid; i < 64 * 64; i += 256) {
            int r = i >> 6, k = i & 63;
            Ws[i] = Wih[(size_t)(nb + r) * HH + kt0 + k];
        }
        __syncthreads();
        for (int n = 0; n < 64; ++n) {
            u64 dpp = pack2(dgs[n * 32 + b], dgs[n * 32 + b]);
            ulonglong2 wa = *(const ulonglong2*)&Ws[n * 64 + kg * 8];
            ulonglong2 wb = *(const ulonglong2*)&Ws[n * 64 + kg * 8 + 4];
            acc[0] = ffma2(wa.x, dpp, acc[0]);
            acc[1] = ffma2(wa.y, dpp, acc[1]);
            acc[2] = ffma2(wb.x, dpp, acc[2]);
            acc[3] = ffma2(wb.y, dpp, acc[3]);
        }
        __syncthreads();
    }
#pragma unroll
    for (int p = 0; p < 4; ++p) {
        float lo, hi; unpack2(acc[p], lo, hi);
        g_dx1[(size_t)t * HB + (size_t)(kt0 + kg * 8 + 2 * p) * BB + b] = lo;
        g_dx1[(size_t)t * HB + (size_t)(kt0 + kg * 8 + 2 * p + 1) * BB + b] = hi;
    }
}

// ================= K4: out[b][t][k] = sum_n dg0[t][n][b] * W_ih0[n][k], k<64 =================
__global__ void __launch_bounds__(256) k_dx(const float* __restrict__ Wih,
                                            float* __restrict__ out) {
    __shared__ float dgs[64 * 32];
    __shared__ float Ws[64 * 64];
    const int tid = threadIdx.x, t = blockIdx.x;
    const int b = tid & 31, kg = tid >> 5;
    u64 acc[4];
#pragma unroll
    for (int m = 0; m < 4; ++m) acc[m] = 0ull;
    for (int nb = 0; nb < GG; nb += 64) {
        for (int i = tid; i < 64 * 32; i += 256)
            dgs[i] = g_xg0[(size_t)t * GB + (size_t)nb * BB + i];
        for (int i = tid; i < 64 * 64; i += 256) {
            int r = i >> 6, k = i & 63;
            Ws[i] = Wih[(size_t)(nb + r) * NIN + k];
        }
        __syncthreads();
        for (int n = 0; n < 64; ++n) {
            u64 dpp = pack2(dgs[n * 32 + b], dgs[n * 32 + b]);
            ulonglong2 wa = *(const ulonglong2*)&Ws[n * 64 + kg * 8];
            ulonglong2 wb = *(const ulonglong2*)&Ws[n * 64 + kg * 8 + 4];
            acc[0] = ffma2(wa.x, dpp, acc[0]);
            acc[1] = ffma2(wa.y, dpp, acc[1]);
            acc[2] = ffma2(wb.x, dpp, acc[2]);
            acc[3] = ffma2(wb.y, dpp, acc[3]);
        }
        __syncthreads();
    }
#pragma unroll
    for (int p = 0; p < 4; ++p) {
        float lo, hi; unpack2(acc[p], lo, hi);
        out[((size_t)b * TT + t) * NIN + kg * 8 + 2 * p] = lo;
        out[((size_t)b * TT + t) * NIN + kg * 8 + 2 * p + 1] = hi;
    }
}

// ================= persistent LSTM forward (512 threads/CTA) =================
// CTA owns 4 h-columns (j0..j0+3) -> 16 gate rows.
// smem: sW[16][512] 32KB | sh2[32][514] ~64KB | sred[4][512] 8KB | sact[512] 2KB
#define SH2_STRIDE 514
#define FWD_SMEM ((16 * 512 + 32 * SH2_STRIDE + 4 * 512 + 512) * 4)
__global__ void __launch_bounds__(512, 1) lstm_fwd_kernel(const float* __restrict__ Whh,
                                                          int layer) {
    extern __shared__ float smem[];
    float* sW = smem;                            // 8192
    float* sh2 = smem + 16 * 512;                // 32*514, layout [b][k]
    float* sred = sh2 + 32 * SH2_STRIDE;         // 2048
    float* sact = sred + 2048;                   // 512

    float* gates = layer ? g_xg1 : g_xg0;
    float* cbuf = layer ? g_c1 : g_c0;

    const int tid = threadIdx.x, j0 = blockIdx.x * 4;
    const int b = tid & 31, wid = tid >> 5;      // 16 warps
    const int rg = wid & 3, kh = wid >> 2;       // 4 row-groups x 4 k-quarters
    const int rho = wid;                          // phase-B gate row = wid? no: rho = tid>>5
    // phase-B mapping: value q = tid = rho*32 + bb
    const int q_rho = tid >> 5, q_bb = tid & 31;
    const int q_n = (q_rho >> 2) * HH + j0 + (q_rho & 3);

    for (int i = tid; i < 16 * 512; i += 512) {
        int r = i >> 9, k = i & 511;
        int n = (r >> 2) * HH + j0 + (r & 3);
        sW[i] = Whh[(size_t)n * HH + k];
    }
    unsigned gen0 = *((volatile unsigned*)&g_bar_gen);
    float creg = 0.f;
    __syncthreads();

    for (int t = 0; t < TT; ++t) {
        size_t tg = (size_t)t * GB;
        // prefetch xg value for this thread's gate (independent of barrier)
        float pre_xg = gates[tg + (size_t)q_n * BB + q_bb];

        // stage h_{t-1} transposed into sh2[b][k]
        if (t == 0) {
            for (int i = tid; i < 32 * SH2_STRIDE / 2; i += 512)
                ((u64*)sh2)[i] = 0ull;
        } else {
            const float* src = g_hT + (size_t)(t - 1) * HB;   // [b][j]
#pragma unroll
            for (int r = 0; r < 8; ++r) {
                int i4 = tid + r * 512;
                float4 v = *(const float4*)&src[i4 * 4];
                int bb = i4 >> 7;
                int k = (i4 & 127) * 4;
                float* dst = &sh2[bb * SH2_STRIDE + k];
                *(float2*)dst = make_float2(v.x, v.y);
                *(float2*)(dst + 2) = make_float2(v.z, v.w);
            }
        }
        __syncthreads();

        // packed matmul: 4 rows (rg), k quarter (kh, 128 wide), lane b
        u64 acc0 = 0ull, acc1 = 0ull, acc2 = 0ull, acc3 = 0ull;
        const float* w0p = sW + (rg * 4 + 0) * 512;
        const float* w1p = sW + (rg * 4 + 1) * 512;
        const float* w2p = sW + (rg * 4 + 2) * 512;
        const float* w3p = sW + (rg * 4 + 3) * 512;
        const float* hp = sh2 + b * SH2_STRIDE;
        const int kb = kh * 128;
#pragma unroll 4
        for (int k = kb; k < kb + 128; k += 4) {
            u64 h01 = *(const u64*)(hp + k);
            u64 h23 = *(const u64*)(hp + k + 2);
            ulonglong2 w0 = *(const ulonglong2*)(w0p + k);
            ulonglong2 w1 = *(const ulonglong2*)(w1p + k);
            ulonglong2 w2 = *(const ulonglong2*)(w2p + k);
            ulonglong2 w3 = *(const ulonglong2*)(w3p + k);
            acc0 = ffma2(w0.x, h01, acc0); acc0 = ffma2(w0.y, h23, acc0);
            acc1 = ffma2(w1.x, h01, acc1); acc1 = ffma2(w1.y, h23, acc1);
            acc2 = ffma2(w2.x, h01, acc2); acc2 = ffma2(w2.y, h23, acc2);
            acc3 = ffma2(w3.x, h01, acc3); acc3 = ffma2(w3.y, h23, acc3);
        }
        float lo, hi;
        unpack2(acc0, lo, hi); sred[kh * 512 + (rg * 4 + 0) * 32 + b] = lo + hi;
        unpack2(acc1, lo, hi); sred[kh * 512 + (rg * 4 + 1) * 32 + b] = lo + hi;
        unpack2(acc2, lo, hi); sred[kh * 512 + (rg * 4 + 2) * 32 + b] = lo + hi;
        unpack2(acc3, lo, hi); sred[kh * 512 + (rg * 4 + 3) * 32 + b] = lo + hi;
        __syncthreads();

        // phase B: exactly one gate value per thread
        {
            float g = sred[tid] + sred[512 + tid] + sred[1024 + tid] + sred[1536 + tid] + pre_xg;
            float v = (q_rho >= 8 && q_rho < 12) ? tanhf(g) : sigf(g);
            sact[tid] = v;
            gates[tg + (size_t)q_n * BB + q_bb] = v;
        }
        __syncthreads();

        // phase C: c/h update (tid<128)
        if (tid < 128) {
            int jl = tid >> 5, bb = tid & 31;
            float iv = sact[(0 + jl) * 32 + bb];
            float fv = sact[(4 + jl) * 32 + bb];
            float gv = sact[(8 + jl) * 32 + bb];
            float ov = sact[(12 + jl) * 32 + bb];
            float c = fv * creg + iv * gv;
            creg = c;
            float h = ov * tanhf(c);
            int j = j0 + jl;
            cbuf[(size_t)t * HB + (size_t)j * BB + bb] = c;
            g_hT[(size_t)t * HB + (size_t)bb * HH + j] = h;
            if (layer == 0)
                g_h0[(size_t)t * HB + (size_t)j * BB + bb] = h;
        }
        grid_barrier(gen0 + (unsigned)(t + 1));
    }
}

// ================= persistent LSTM backward (512 threads/CTA) =================
// CTA owns 8 j x 16 b. Full dg[t+1] slice staged at once (128KB).
// smem: sWc[2048][8] 64KB | sdg[2048][16] 128KB | sred[16][8][16] 8KB -> 200KB
#define BWD_SMEM ((2048 * 8 + 2048 * 16 + 2048) * 4)
__global__ void __launch_bounds__(512, 1) lstm_bwd_kernel(const float* __restrict__ Whh,
                                                          const float* __restrict__ Wout,
                                                          int layer) {
    extern __shared__ float smem[];
    float* sWc = smem;                 // 16384
    float* sdg = smem + 2048 * 8;      // 32768
    float* sred = sdg + 2048 * 16;     // 2048

    float* gates = layer ? g_xg1 : g_xg0;
    const float* cbuf = layer ? g_c1 : g_c0;

    const int tid = threadIdx.x;
    const int j0 = (blockIdx.x >> 1) * 8;
    const int b0 = (blockIdx.x & 1) * 16;
    const int wid = tid >> 5;                 // 16 warps -> n-block of 128
    const int jg = (tid >> 4) & 1, bl = tid & 15;
    const int cjj = tid >> 4, cbl = tid & 15; // phase-C mapping (tid<128)

    for (int i = tid; i < 2048 * 2; i += 512) {
        int n = i >> 1, q = i & 1;
        *(float4*)&sWc[n * 8 + q * 4] = *(const float4*)&Whh[(size_t)n * HH + j0 + q * 4];
    }
    unsigned gen0 = *((volatile unsigned*)&g_bar_gen);
    float dcreg = 0.f;
    float dho_c = 0.f;
    if (layer == 1 && tid < 128) dho_c = Wout[j0 + cjj];
    __syncthreads();

    for (int t = TT - 1; t >= 0; --t) {
        // ---- prefetch all barrier-independent operands (tid<128) ----
        float p_iv = 0.f, p_fv = 0.f, p_gv = 0.f, p_ov = 0.f;
        float p_c = 0.f, p_cprev = 0.f, p_dho = 0.f;
        size_t gb = 0, co = 0;
        if (tid < 128) {
            int j = j0 + cjj, b = b0 + cbl;
            gb = (size_t)t * GB + (size_t)j * BB + b;
            co = (size_t)t * HB + (size_t)j * BB + b;
            p_iv = gates[gb];
            p_fv = gates[gb + (size_t)512 * BB];
            p_gv = gates[gb + (size_t)1024 * BB];
            p_ov = gates[gb + (size_t)1536 * BB];
            p_c = cbuf[co];
            p_cprev = (t > 0) ? cbuf[co - HB] : 0.f;
            p_dho = (layer == 1) ? dho_c : g_dx1[co];
        }

        u64 accA = 0ull, accB = 0ull;
        if (t < TT - 1) {
            // stage full dg[t+1][n][b0..b0+15] slice: 8192 float4, 16/thread
            const float* dgp = gates + (size_t)(t + 1) * GB;
#pragma unroll 4
            for (int r = 0; r < 16; ++r) {
                int f4 = tid + r * 512;
                int nl = f4 >> 2, bq = f4 & 3;
                *(float4*)&sdg[nl * 16 + bq * 4] =
                    *(const float4*)&dgp[(size_t)nl * BB + b0 + bq * 4];
            }
            __syncthreads();
            const int nbeg = wid * 128;
#pragma unroll 4
            for (int n = nbeg; n < nbeg + 128; ++n) {
                float dgv = sdg[n * 16 + bl];
                u64 dpp = pack2(dgv, dgv);
                ulonglong2 wp = *(const ulonglong2*)&sWc[n * 8 + jg * 4];
                accA = ffma2(wp.x, dpp, accA);
                accB = ffma2(wp.y, dpp, accB);
            }
            __syncthreads();   // protect sdg before next-step restage (after sred write below would also do; keep simple)
        }
        {
            float lo, hi;
            unpack2(accA, lo, hi);
            sred[wid * 128 + (jg * 4 + 0) * 16 + bl] = lo;
            sred[wid * 128 + (jg * 4 + 1) * 16 + bl] = hi;
            unpack2(accB, lo, hi);
            sred[wid * 128 + (jg * 4 + 2) * 16 + bl] = lo;
            sred[wid * 128 + (jg * 4 + 3) * 16 + bl] = hi;
        }
        __syncthreads();

        if (tid < 128) {
            float dhrec = 0.f;
#pragma unroll
            for (int h = 0; h < 16; ++h) dhrec += sred[h * 128 + cjj * 16 + cbl];
            float dh = p_dho + dhrec;
            float tc = tanhf(p_c);
            float dc = dcreg + dh * p_ov * (1.f - tc * tc);
            float dgi = (dc * p_gv) * p_iv * (1.f - p_iv);
            float dgf = (dc * p_cprev) * p_fv * (1.f - p_fv);
            float dgg = (dc * p_iv) * (1.f - p_gv * p_gv);
            float dgo = (dh * tc) * p_ov * (1.f - p_ov);
            dcreg = dc * p_fv;
            gates[gb] = dgi;
            gates[gb + (size_t)512 * BB] = dgf;
            gates[gb + (size_t)1024 * BB] = dgg;
            gates[gb + (size_t)1536 * BB] = dgo;
        }
        grid_barrier(gen0 + (unsigned)(TT - t));
    }
}

extern "C" void kernel_launch(void* const* d_in, const int* in_sizes, int n_in,
                              void* d_out, int out_size) {
    const float* x    = (const float*)d_in[0];
    const float* Wih0 = (const float*)d_in[1];
    const float* Whh0 = (const float*)d_in[2];
    const float* bih0 = (const float*)d_in[3];
    const float* bhh0 = (const float*)d_in[4];
    const float* Wih1 = (const float*)d_in[5];
    const float* Whh1 = (const float*)d_in[6];
    const float* bih1 = (const float*)d_in[7];
    const float* bhh1 = (const float*)d_in[8];
    const float* Wout = (const float*)d_in[9];
    float* out = (float*)d_out;

    cudaFuncSetAttribute(lstm_fwd_kernel, cudaFuncAttributeMaxDynamicSharedMemorySize, FWD_SMEM);
    cudaFuncSetAttribute(lstm_bwd_kernel, cudaFuncAttributeMaxDynamicSharedMemorySize, BWD_SMEM);

    k_xg0<<<dim3(16, 512), 256>>>(x, Wih0, bih0, bhh0);
    lstm_fwd_kernel<<<NB, 512, FWD_SMEM>>>(Whh0, 0);
    k_xg1<<<dim3(32, 512), 256>>>(Wih1, bih1, bhh1);
    lstm_fwd_kernel<<<NB, 512, FWD_SMEM>>>(Whh1, 1);
    lstm_bwd_kernel<<<NB, 512, BWD_SMEM>>>(Whh1, Wout, 1);
    k_dx1<<<dim3(8, 512), 256>>>(Wih1);
    lstm_bwd_kernel<<<NB, 512, BWD_SMEM>>>(Whh0, Wout, 0);
    k_dx<<<512, 256>>>(Wih0, out);
}